// round 8
// baseline (speedup 1.0000x reference)
#include <cuda_runtime.h>

// ---------------------------------------------------------------------------
// InteractingLayer fused kernel (fp32, packed f32x2 FMA)
//   x[B,40,64] -> q,k,v,r = x@W^T + b  (4x [40,128] per batch, in SMEM)
//   S = softmax(q k^T / 8) per head (H=4, D=32), out = relu(S v + r)
// One CTA per batch, 256 threads, everything staged through shared memory.
// ---------------------------------------------------------------------------

#define Fd   40
#define Ed   64
#define Hd   4
#define Dd   32
#define OUTd 128

// SMEM layout (float offsets)
#define OFF_XS 0                    // xs[40][65]           = 2600
#define OFF_WT 2600                 // wt[2][64][130]       = 16640
#define OFF_QS 19240                // qs[40][132]          = 5280
#define OFF_KS 24520                // ks[40][132]
#define OFF_VS 29800                // vs[40][132]
#define OFF_RS 35080                // rs[40][132]
#define OFF_SS 40360                // ss[4][1764] (40x44 rows + head pad)
#define SMEM_FLOATS 47416
#define SMEM_BYTES  (SMEM_FLOATS * 4)

#define SS_HEAD 1764
#define SS_ROW  44

typedef unsigned long long ull;

__device__ __forceinline__ ull pk2(float a, float b) {
    ull r;
    asm("mov.b64 %0, {%1,%2};" : "=l"(r) : "f"(a), "f"(b));
    return r;
}
__device__ __forceinline__ void unpk2(ull v, float& a, float& b) {
    asm("mov.b64 {%0,%1}, %2;" : "=f"(a), "=f"(b) : "l"(v));
}
__device__ __forceinline__ ull ffma2(ull a, ull b, ull c) {
    ull d;
    asm("fma.rn.f32x2 %0, %1, %2, %3;" : "=l"(d) : "l"(a), "l"(b), "l"(c));
    return d;
}

__global__ __launch_bounds__(256, 1)
void interacting_layer_kernel(
    const float* __restrict__ x,
    const float* __restrict__ Wq, const float* __restrict__ bq,
    const float* __restrict__ Wk, const float* __restrict__ bk,
    const float* __restrict__ Wv, const float* __restrict__ bv,
    const float* __restrict__ Wr, const float* __restrict__ br,
    float* __restrict__ out)
{
    extern __shared__ float sm[];
    float* xs = sm + OFF_XS;
    float* wt = sm + OFF_WT;
    float* qs = sm + OFF_QS;
    float* ks = sm + OFF_KS;
    float* vs = sm + OFF_VS;
    float* rs = sm + OFF_RS;
    float* ss = sm + OFF_SS;

    const int b = blockIdx.x;
    const int t = threadIdx.x;

    // ---- load x tile [40][64] -> xs[40][65] (padded) -------------------
    const float* xb = x + (size_t)b * (Fd * Ed);
    for (int i = t; i < Fd * Ed; i += 256) {
        int f = i >> 6, e = i & 63;
        xs[f * 65 + e] = xb[i];
    }

    // ---- projections: q,k,v,r = x @ W^T + bias -------------------------
    // thread tile: 5 rows x 8 cols (4 column PAIRS, packed f32x2)
    const int mm = t >> 7;            // which matrix of the current pair
    const int q2 = t & 127;
    const int fT = q2 >> 4;           // 0..7  -> rows f0..f0+4
    const int cT = q2 & 15;           // 0..15 -> col pairs {2cT+32j, 2cT+32j+1}
    const int f0 = fT * 5;

    for (int s = 0; s < 2; s++) {
        __syncthreads();  // covers xs on s=0, wt-read completion on s=1

        // stage W pair transposed: wt[m][e][col] = W[col*64+e]
        const float* W0 = s ? Wv : Wq;
        const float* W1 = s ? Wr : Wk;
        for (int i = t; i < 2 * OUTd * Ed; i += 256) {
            int wm  = i >> 13;
            int r   = i & 8191;
            int col = r >> 6;
            int e   = r & 63;
            wt[wm * 8320 + e * 130 + col] = (wm ? W1 : W0)[r];
        }
        __syncthreads();

        const float* myW = wt + mm * 8320 + 2 * cT;
        const float* myB = s ? (mm ? br : bv) : (mm ? bk : bq);
        float*       myO = s ? (mm ? rs : vs) : (mm ? ks : qs);

        ull acc[5][4];
#pragma unroll
        for (int jp = 0; jp < 4; jp++) {
            float b0 = __ldg(myB + 2 * cT + 32 * jp);
            float b1 = __ldg(myB + 2 * cT + 32 * jp + 1);
            ull bb = pk2(b0, b1);
#pragma unroll
            for (int i = 0; i < 5; i++) acc[i][jp] = bb;
        }

#pragma unroll 8
        for (int e = 0; e < Ed; e++) {
            ull w2[4];
#pragma unroll
            for (int jp = 0; jp < 4; jp++)
                w2[jp] = *(const ull*)(myW + e * 130 + 32 * jp);
            ull xx[5];
#pragma unroll
            for (int i = 0; i < 5; i++) {
                float v = xs[(f0 + i) * 65 + e];
                xx[i] = pk2(v, v);
            }
#pragma unroll
            for (int i = 0; i < 5; i++)
#pragma unroll
                for (int jp = 0; jp < 4; jp++)
                    acc[i][jp] = ffma2(xx[i], w2[jp], acc[i][jp]);
        }

#pragma unroll
        for (int i = 0; i < 5; i++)
#pragma unroll
            for (int jp = 0; jp < 4; jp++)
                *(ull*)(myO + (f0 + i) * 132 + 2 * cT + 32 * jp) = acc[i][jp];
    }
    __syncthreads();

    // ---- attention scores: S[h][f][g] = (q.k)/8 ------------------------
    {
        const int h   = t >> 6;
        const int rst = t & 63;
        const int fT2 = rst >> 3;
        const int gT  = rst & 7;
        const int f0s = fT2 * 5;
        const int g0  = gT * 5;

        float sa[5][5];
#pragma unroll
        for (int i = 0; i < 5; i++)
#pragma unroll
            for (int j = 0; j < 5; j++) sa[i][j] = 0.f;

        const float* qb = qs + h * Dd;
        const float* kb = ks + h * Dd;
#pragma unroll 4
        for (int d = 0; d < Dd; d++) {
            float qv[5], kv[5];
#pragma unroll
            for (int i = 0; i < 5; i++) qv[i] = qb[(f0s + i) * 132 + d];
#pragma unroll
            for (int j = 0; j < 5; j++) kv[j] = kb[(g0 + j) * 132 + d];
#pragma unroll
            for (int i = 0; i < 5; i++)
#pragma unroll
                for (int j = 0; j < 5; j++)
                    sa[i][j] = fmaf(qv[i], kv[j], sa[i][j]);
        }
#pragma unroll
        for (int i = 0; i < 5; i++)
#pragma unroll
            for (int j = 0; j < 5; j++)
                ss[h * SS_HEAD + (f0s + i) * SS_ROW + g0 + j] = sa[i][j] * 0.125f;
    }
    __syncthreads();

    // ---- softmax over g (160 rows) --------------------------------------
    if (t < Hd * Fd) {
        const int hh = t / Fd;
        const int ff = t % Fd;
        float* row = ss + hh * SS_HEAD + ff * SS_ROW;
        float mx = row[0];
#pragma unroll 8
        for (int g = 1; g < Fd; g++) mx = fmaxf(mx, row[g]);
        float sum = 0.f;
#pragma unroll 8
        for (int g = 0; g < Fd; g++) {
            float v = __expf(row[g] - mx);
            row[g] = v;
            sum += v;
        }
        float inv = 1.f / sum;
#pragma unroll 8
        for (int g = 0; g < Fd; g++) row[g] *= inv;
    }
    __syncthreads();

    // ---- out = relu(S @ v + r) ------------------------------------------
    {
        const int fT3 = t >> 5;
        const int oT  = t & 31;
        const int f0a = fT3 * 5;
        const int o0  = oT * 4;          // 4 output cols, never straddles heads
        const int h2  = o0 >> 5;

        ull a2[5][2];
#pragma unroll
        for (int i = 0; i < 5; i++) {
            a2[i][0] = *(const ull*)(rs + (f0a + i) * 132 + o0);
            a2[i][1] = *(const ull*)(rs + (f0a + i) * 132 + o0 + 2);
        }
        const float* sb = ss + h2 * SS_HEAD;
#pragma unroll 4
        for (int g = 0; g < Fd; g++) {
            float4 vv = *(const float4*)(vs + g * 132 + o0);
            ull v01 = pk2(vv.x, vv.y);
            ull v23 = pk2(vv.z, vv.w);
#pragma unroll
            for (int i = 0; i < 5; i++) {
                float svv = sb[(f0a + i) * SS_ROW + g];
                ull sp = pk2(svv, svv);
                a2[i][0] = ffma2(sp, v01, a2[i][0]);
                a2[i][1] = ffma2(sp, v23, a2[i][1]);
            }
        }
        float* ob = out + (size_t)b * (Fd * OUTd);
#pragma unroll
        for (int i = 0; i < 5; i++) {
            float v0, v1, v2, v3;
            unpk2(a2[i][0], v0, v1);
            unpk2(a2[i][1], v2, v3);
            float4 r4;
            r4.x = fmaxf(v0, 0.f);
            r4.y = fmaxf(v1, 0.f);
            r4.z = fmaxf(v2, 0.f);
            r4.w = fmaxf(v3, 0.f);
            *(float4*)(ob + (f0a + i) * OUTd + o0) = r4;
        }
    }
}

extern "C" void kernel_launch(void* const* d_in, const int* in_sizes, int n_in,
                              void* d_out, int out_size)
{
    const float* x  = (const float*)d_in[0];
    const float* Wq = (const float*)d_in[1];
    const float* bq = (const float*)d_in[2];
    const float* Wk = (const float*)d_in[3];
    const float* bk = (const float*)d_in[4];
    const float* Wv = (const float*)d_in[5];
    const float* bv = (const float*)d_in[6];
    const float* Wr = (const float*)d_in[7];
    const float* br = (const float*)d_in[8];
    float* out = (float*)d_out;

    const int B = in_sizes[0] / (Fd * Ed);

    static int attr_set = 0;
    if (!attr_set) {
        cudaFuncSetAttribute(interacting_layer_kernel,
                             cudaFuncAttributeMaxDynamicSharedMemorySize,
                             SMEM_BYTES);
        attr_set = 1;
    }

    interacting_layer_kernel<<<B, 256, SMEM_BYTES>>>(
        x, Wq, bq, Wk, bk, Wv, bv, Wr, br, out);
}

// round 10
// speedup vs baseline: 1.1312x; 1.1312x over previous
#include <cuda_runtime.h>

// ---------------------------------------------------------------------------
// InteractingLayer fused kernel v2.1 (fp32, packed f32x2 FMA, 512 thr/CTA)
//   q,k,v,r = x@W^T + b ; S = softmax(q k^T / 8) per head (H=4, D=32)
//   out = relu(S v + r).  One CTA per batch. Weights staged once (all 4),
//   score buffer overlays the dead weight region.
//   v2.1 fix: WT_STRIDE must be EVEN (8-byte ull loads) -> 130.
// ---------------------------------------------------------------------------

#define Fd   40
#define Ed   64
#define OUTd 128

#define XS_STRIDE 68
#define WT_STRIDE 130                  /* EVEN: ull loads need 8B alignment */
#define WT_MAT    (64 * WT_STRIDE)     /* 8320 */
#define QR_STRIDE 132
#define SS_ROW    44
#define SS_HEAD   1764

#define OFF_XS 0                                   /* 40*68   = 2720  */
#define OFF_WT 2720                                /* 4*8320  = 33280 */
#define OFF_QS (OFF_WT + 4 * WT_MAT)               /* 36000           */
#define OFF_KS (OFF_QS + Fd * QR_STRIDE)
#define OFF_VS (OFF_KS + Fd * QR_STRIDE)
#define OFF_RS (OFF_VS + Fd * QR_STRIDE)
#define SMEM_FLOATS (OFF_RS + Fd * QR_STRIDE)      /* 57120 -> 228480 B */
#define SMEM_BYTES  (SMEM_FLOATS * 4)

#define OFF_SS OFF_WT                              /* overlay: 4*1764=7056 */

typedef unsigned long long ull;

__device__ __forceinline__ ull pk2(float a, float b) {
    ull r; asm("mov.b64 %0, {%1,%2};" : "=l"(r) : "f"(a), "f"(b)); return r;
}
__device__ __forceinline__ void unpk2(ull v, float& a, float& b) {
    asm("mov.b64 {%0,%1}, %2;" : "=f"(a), "=f"(b) : "l"(v));
}
__device__ __forceinline__ ull ffma2(ull a, ull b, ull c) {
    ull d; asm("fma.rn.f32x2 %0, %1, %2, %3;" : "=l"(d) : "l"(a), "l"(b), "l"(c));
    return d;
}

__global__ __launch_bounds__(512, 1)
void interacting_layer_kernel(
    const float* __restrict__ x,
    const float* __restrict__ Wq, const float* __restrict__ bq,
    const float* __restrict__ Wk, const float* __restrict__ bk,
    const float* __restrict__ Wv, const float* __restrict__ bv,
    const float* __restrict__ Wr, const float* __restrict__ br,
    float* __restrict__ out)
{
    extern __shared__ float sm[];
    float* xs = sm + OFF_XS;
    float* wt = sm + OFF_WT;
    float* qs = sm + OFF_QS;
    float* ks = sm + OFF_KS;
    float* vs = sm + OFF_VS;
    float* rs = sm + OFF_RS;
    float* ss = sm + OFF_SS;

    const int b = blockIdx.x;
    const int t = threadIdx.x;

    // ================= stage: x tile (float4) + 4 weight matrices ========
    {
        const float4* x4 = (const float4*)(x + (size_t)b * (Fd * Ed));
        for (int i = t; i < Fd * Ed / 4; i += 512) {           // 640 float4
            int f = i >> 4, e4 = i & 15;
            *(float4*)(xs + f * XS_STRIDE + e4 * 4) = x4[i];
        }
        // wt[m][e][col] = W_m[col*64+e]; coalesced GMEM, 2-way STS conflict
        for (int i = t; i < 4 * OUTd * Ed; i += 512) {         // 64 iters
            int m   = i >> 13;
            int r   = i & 8191;
            int col = r >> 6;
            int e   = r & 63;
            const float* Wm = (m == 0) ? Wq : (m == 1) ? Wk : (m == 2) ? Wv : Wr;
            wt[m * WT_MAT + e * WT_STRIDE + col] = Wm[r];
        }
    }
    __syncthreads();

    // ================= projections: all 4 matrices concurrently ==========
    // 128 threads per matrix; thread tile 5 rows x 8 cols (4 col pairs)
    {
        const int mat = t >> 7;
        const int q2  = t & 127;
        const int fT  = q2 >> 4;
        const int cT  = q2 & 15;
        const int f0  = fT * 5;

        const float* myW = wt + mat * WT_MAT + 2 * cT;
        const float* myB = (mat == 0) ? bq : (mat == 1) ? bk : (mat == 2) ? bv : br;
        float*       myO = (mat == 0) ? qs : (mat == 1) ? ks : (mat == 2) ? vs : rs;

        ull acc[5][4];
#pragma unroll
        for (int jp = 0; jp < 4; jp++) {
            float b0 = __ldg(myB + 2 * cT + 32 * jp);
            float b1 = __ldg(myB + 2 * cT + 32 * jp + 1);
            ull bb = pk2(b0, b1);
#pragma unroll
            for (int i = 0; i < 5; i++) acc[i][jp] = bb;
        }

#pragma unroll 4
        for (int e = 0; e < Ed; e++) {
            ull w2[4];
#pragma unroll
            for (int jp = 0; jp < 4; jp++)
                w2[jp] = *(const ull*)(myW + e * WT_STRIDE + 32 * jp);
            ull xx[5];
#pragma unroll
            for (int i = 0; i < 5; i++) {
                float v = xs[(f0 + i) * XS_STRIDE + e];
                xx[i] = pk2(v, v);
            }
#pragma unroll
            for (int i = 0; i < 5; i++)
#pragma unroll
                for (int jp = 0; jp < 4; jp++)
                    acc[i][jp] = ffma2(xx[i], w2[jp], acc[i][jp]);
        }

#pragma unroll
        for (int i = 0; i < 5; i++)
#pragma unroll
            for (int jp = 0; jp < 4; jp++)
                *(ull*)(myO + (f0 + i) * QR_STRIDE + 2 * cT + 32 * jp) = acc[i][jp];
    }
    __syncthreads();   // wt dead from here; ss overlay becomes live

    // ================= scores: S[h][f][g] = (q.k)/8 (packed over d) ======
    if (t < 256) {
        const int h   = t >> 6;
        const int rst = t & 63;
        const int f0s = (rst >> 3) * 5;
        const int g0  = (rst & 7) * 5;

        ull acc2[5][5];
#pragma unroll
        for (int i = 0; i < 5; i++)
#pragma unroll
            for (int j = 0; j < 5; j++) acc2[i][j] = 0ull;

        const float* qb = qs + h * 32;
        const float* kb = ks + h * 32;
#pragma unroll 4
        for (int dp = 0; dp < 16; dp++) {
            ull qv[5], kv[5];
#pragma unroll
            for (int i = 0; i < 5; i++)
                qv[i] = *(const ull*)(qb + (f0s + i) * QR_STRIDE + 2 * dp);
#pragma unroll
            for (int j = 0; j < 5; j++)
                kv[j] = *(const ull*)(kb + (g0 + j) * QR_STRIDE + 2 * dp);
#pragma unroll
            for (int i = 0; i < 5; i++)
#pragma unroll
                for (int j = 0; j < 5; j++)
                    acc2[i][j] = ffma2(qv[i], kv[j], acc2[i][j]);
        }
#pragma unroll
        for (int i = 0; i < 5; i++)
#pragma unroll
            for (int j = 0; j < 5; j++) {
                float a0, a1;
                unpk2(acc2[i][j], a0, a1);
                ss[h * SS_HEAD + (f0s + i) * SS_ROW + g0 + j] = (a0 + a1) * 0.125f;
            }
    }
    __syncthreads();

    // ================= softmax: 2 threads per row, shfl combine ==========
    if (t < 320) {
        const int row  = t >> 1;           // 0..159
        const int half = t & 1;
        const int hh   = row / 40;
        const int ff   = row - hh * 40;
        float* rp = ss + hh * SS_HEAD + ff * SS_ROW + half * 20;

        float v[20];
#pragma unroll
        for (int g = 0; g < 20; g++) v[g] = rp[g];
        float mx = v[0];
#pragma unroll
        for (int g = 1; g < 20; g++) mx = fmaxf(mx, v[g]);
        mx = fmaxf(mx, __shfl_xor_sync(0xffffffffu, mx, 1));
        float sum = 0.f;
#pragma unroll
        for (int g = 0; g < 20; g++) { v[g] = __expf(v[g] - mx); sum += v[g]; }
        sum += __shfl_xor_sync(0xffffffffu, sum, 1);
        float inv = 1.f / sum;
#pragma unroll
        for (int g = 0; g < 20; g++) rp[g] = v[g] * inv;
    }
    __syncthreads();

    // ================= out = relu(S @ v + r) ==============================
    // 128 threads, tile 10 rows x 4 cols; g consumed in pairs (float2 s).
    if (t < 128) {
        const int cg  = t & 31;            // col group: cols 4cg..4cg+3
        const int rg  = t >> 5;            // 0..3 -> rows rg*10..+9
        const int o0  = cg * 4;
        const int f0a = rg * 10;
        const int h2  = cg >> 3;           // head of this col group

        ull acc[10][2];
#pragma unroll
        for (int i = 0; i < 10; i++) {
            acc[i][0] = *(const ull*)(rs + (f0a + i) * QR_STRIDE + o0);
            acc[i][1] = *(const ull*)(rs + (f0a + i) * QR_STRIDE + o0 + 2);
        }

        const float* sb = ss + h2 * SS_HEAD;
#pragma unroll 2
        for (int g = 0; g < Fd; g += 2) {
            ull va0 = *(const ull*)(vs + g * QR_STRIDE + o0);
            ull va1 = *(const ull*)(vs + g * QR_STRIDE + o0 + 2);
            ull vb0 = *(const ull*)(vs + (g + 1) * QR_STRIDE + o0);
            ull vb1 = *(const ull*)(vs + (g + 1) * QR_STRIDE + o0 + 2);
#pragma unroll
            for (int i = 0; i < 10; i++) {
                float2 s2 = *(const float2*)(sb + (f0a + i) * SS_ROW + g);
                ull sa  = pk2(s2.x, s2.x);
                ull sbp = pk2(s2.y, s2.y);
                acc[i][0] = ffma2(sa, va0, acc[i][0]);
                acc[i][1] = ffma2(sa, va1, acc[i][1]);
                acc[i][0] = ffma2(sbp, vb0, acc[i][0]);
                acc[i][1] = ffma2(sbp, vb1, acc[i][1]);
            }
        }

        float* ob = out + (size_t)b * (Fd * OUTd);
#pragma unroll
        for (int i = 0; i < 10; i++) {
            float v0, v1, v2, v3;
            unpk2(acc[i][0], v0, v1);
            unpk2(acc[i][1], v2, v3);
            float4 r4;
            r4.x = fmaxf(v0, 0.f);
            r4.y = fmaxf(v1, 0.f);
            r4.z = fmaxf(v2, 0.f);
            r4.w = fmaxf(v3, 0.f);
            *(float4*)(ob + (f0a + i) * OUTd + o0) = r4;
        }
    }
}

extern "C" void kernel_launch(void* const* d_in, const int* in_sizes, int n_in,
                              void* d_out, int out_size)
{
    const float* x  = (const float*)d_in[0];
    const float* Wq = (const float*)d_in[1];
    const float* bq = (const float*)d_in[2];
    const float* Wk = (const float*)d_in[3];
    const float* bk = (const float*)d_in[4];
    const float* Wv = (const float*)d_in[5];
    const float* bv = (const float*)d_in[6];
    const float* Wr = (const float*)d_in[7];
    const float* br = (const float*)d_in[8];
    float* out = (float*)d_out;

    const int B = in_sizes[0] / (Fd * Ed);

    static int attr_set = 0;
    if (!attr_set) {
        cudaFuncSetAttribute(interacting_layer_kernel,
                             cudaFuncAttributeMaxDynamicSharedMemorySize,
                             SMEM_BYTES);
        attr_set = 1;
    }

    interacting_layer_kernel<<<B, 512, SMEM_BYTES>>>(
        x, Wq, bq, Wk, bk, Wv, bv, Wr, br, out);
}